// round 15
// baseline (speedup 1.0000x reference)
#include <cuda_runtime.h>
#include <cuda.h>
#include <cuda_fp16.h>
#include <cstdint>

// ============================================================================
// y = x @ W_mod^T ; W_mod = W with values*0.1 scattered at flip_idx (last wins)
// R15: g_wh ELIMINATED. GEMM pulls raw f32 W panels via 2D TMA, converts
// f32->f16 in-SMEM under the tensor pipe, applies scatter as f32 patches to
// the staging tile (f16->f32->f16 roundtrip exact => bit-identical results).
//   K1: winner + x->f16 swizzled + bucket-count zero      (measured 16.9us)
//   K2: exchange-dedup -> per-(chunk,n_tile) patch buckets
//   K3: GEMM, 3-deep TMA(A f16 1D + B f32 2D) pipeline
// ============================================================================

#define O_DIM  4096
#define I_DIM  4096
#define B_ROWS 256
#define W_ELEMS (O_DIM * I_DIM)
#define X_ELEMS (B_ROWS * I_DIM)
#define NC      32

#define SW128(b) ((b) ^ (((b) >> 3) & 0x70))

// x, chunk-major swizzled: [chunk 32][m_tile 2][sub0 16KB | sub1 16KB]
__device__ __align__(16) __half g_xh[X_ELEMS];
// winner tokens; zero at module load; K2's atomicExch restores all-zero
__device__ int g_aux[W_ELEMS];
// patch buckets: [chunk 32][n_tile 64], <=1024 entries each
__device__ int      g_bcnt[2048];
__device__ unsigned g_bdata[2048 * 1024];

// ----------------------------------------------------------------------------
// K1: fused [winner election | x convert | bcnt zero]
// ----------------------------------------------------------------------------
static constexpr int NB_WIN = 977;
static constexpr int NB_CX  = X_ELEMS / 4 / 256;   // 1024

__global__ void __launch_bounds__(256) stage1_kernel(
    const float4* __restrict__ x, const int* __restrict__ flip, int n) {
    const int bid = blockIdx.x, tid = threadIdx.x;
    if (bid < NB_WIN) {
        const int base = bid * 1024 + tid * 4;
        if (base + 3 < n) {
            const int4 f = *reinterpret_cast<const int4*>(flip + base);
            atomicMax(&g_aux[f.x], base + 1);
            atomicMax(&g_aux[f.y], base + 2);
            atomicMax(&g_aux[f.z], base + 3);
            atomicMax(&g_aux[f.w], base + 4);
        } else {
            for (int k = 0; k < 4; ++k)
                if (base + k < n) atomicMax(&g_aux[flip[base + k]], base + k + 1);
        }
    } else if (bid < NB_WIN + NB_CX) {
        const int i = (bid - NB_WIN) * 256 + tid;
        const int m = i >> 10, kq = (i & 1023) << 2;
        float4 v = __ldcs(x + i);
        uint2 p = make_uint2(
            (uint32_t)__half_as_ushort(__float2half_rn(v.x)) |
            ((uint32_t)__half_as_ushort(__float2half_rn(v.y)) << 16),
            (uint32_t)__half_as_ushort(__float2half_rn(v.z)) |
            ((uint32_t)__half_as_ushort(__float2half_rn(v.w)) << 16));
        const int c = kq >> 7, k0 = kq & 127, sub = k0 >> 6, kk = k0 & 63;
        char* dst = reinterpret_cast<char*>(g_xh)
                  + (size_t)c * 65536 + (m >> 7) * 32768 + sub * 16384
                  + SW128((m & 127) * 128 + kk * 2);
        __stcs(reinterpret_cast<uint2*>(dst), p);
    } else {
        #pragma unroll
        for (int j = 0; j < 8; ++j) g_bcnt[tid * 8 + j] = 0;
    }
}

// ----------------------------------------------------------------------------
// K2: exchange-dedup -> bucket append (8 idx/thread)
// ----------------------------------------------------------------------------
__device__ __forceinline__ void emit_patch(int pos, float v) {
    const int o = pos >> 12, i = pos & 4095;
    const int bucket = (i >> 7) * 64 + (o >> 6);
    const int lp = (o & 63) * 128 + (i & 127);
    const unsigned hb = __half_as_ushort(__float2half_rn(v));
    const int slot = atomicAdd(&g_bcnt[bucket], 1);
    if (slot < 1024)
        g_bdata[bucket * 1024 + slot] = ((unsigned)lp << 16) | hb;
}

__global__ void __launch_bounds__(256) scatter_kernel(
    const int* __restrict__ flip, const float* __restrict__ vals, int n) {
    const int base = (blockIdx.x * 256 + threadIdx.x) * 8;
    if (base + 7 < n) {
        const int4 f0 = *reinterpret_cast<const int4*>(flip + base);
        const int4 f1 = *reinterpret_cast<const int4*>(flip + base + 4);
        int pos[8] = {f0.x, f0.y, f0.z, f0.w, f1.x, f1.y, f1.z, f1.w};
        int old[8];
        #pragma unroll
        for (int k = 0; k < 8; ++k) old[k] = atomicExch(&g_aux[pos[k]], 0);
        #pragma unroll
        for (int k = 0; k < 8; ++k)
            if (old[k]) emit_patch(pos[k], vals[old[k] - 1] * 0.1f);
    } else {
        for (int k = 0; k < 8; ++k)
            if (base + k < n) {
                int p = flip[base + k];
                int o = atomicExch(&g_aux[p], 0);
                if (o) emit_patch(p, vals[o - 1] * 0.1f);
            }
    }
}

// ============================================================================
// K3: GEMM. CTA 128x64, K-chunk 128. 3 x 64KB buffers (A f16 32KB + B f32
// 32KB), bf16 B tile 2 x 16KB ping-pong. Patches applied to f32 staging.
// ============================================================================
static constexpr int A_SUB   = 16384;
static constexpr int BSTG    = 32768;           // B f32 staging offset in buf
static constexpr int BUF     = 65536;
static constexpr int SM_BUF  = 1024;
static constexpr int SM_BF16 = SM_BUF + 3 * BUF;        // 197632
static constexpr int GEMM_SMEM = SM_BF16 + 2 * 16384;   // 230400

__device__ __forceinline__ uint32_t smem_u32(const void* p) {
    uint32_t a;
    asm("{ .reg .u64 t; cvta.to.shared.u64 t, %1; cvt.u32.u64 %0, t; }"
        : "=r"(a) : "l"(p));
    return a;
}
__device__ __forceinline__ void ldsm4(uint32_t* r, uint32_t addr) {
    asm volatile("ldmatrix.sync.aligned.m8n8.x4.shared.b16 {%0,%1,%2,%3}, [%4];"
                 : "=r"(r[0]), "=r"(r[1]), "=r"(r[2]), "=r"(r[3]) : "r"(addr));
}
__device__ __forceinline__ void mma16816(float* c, const uint32_t* a,
                                         uint32_t b0, uint32_t b1) {
    asm volatile(
        "mma.sync.aligned.m16n8k16.row.col.f32.f16.f16.f32 "
        "{%0,%1,%2,%3}, {%4,%5,%6,%7}, {%8,%9}, {%0,%1,%2,%3};"
        : "+f"(c[0]), "+f"(c[1]), "+f"(c[2]), "+f"(c[3])
        : "r"(a[0]), "r"(a[1]), "r"(a[2]), "r"(a[3]), "r"(b0), "r"(b1));
}

#define MBAR_WAIT(mbar_addr, phase) do {                                         \
    uint32_t _mbar = (uint32_t)(mbar_addr);                                      \
    uint32_t _parity = (uint32_t)(phase);                                        \
    uint32_t _done;                                                              \
    asm volatile(                                                                \
        "{\n\t.reg .pred p;\n\t"                                                 \
        "mbarrier.try_wait.parity.acquire.cta.shared::cta.b64 p, [%1], %2;\n\t"  \
        "selp.b32 %0, 1, 0, p;\n\t}"                                             \
        : "=r"(_done) : "r"(_mbar), "r"(_parity) : "memory");                    \
    if (!_done) {                                                                \
        asm volatile(                                                            \
            "{\n\t.reg .pred P1;\n\t"                                            \
            "WL_%=:\n\t"                                                         \
            "mbarrier.try_wait.parity.acquire.cta.shared::cta.b64 P1, [%0], %1, 0x989680;\n\t" \
            "@P1 bra.uni WD_%=;\n\t"                                             \
            "bra.uni WL_%=;\n\t"                                                 \
            "WD_%=:\n\t}"                                                        \
            :: "r"(_mbar), "r"(_parity) : "memory");                             \
    }                                                                            \
} while (0)

// Issue A f16 (1D bulk, 32KB) + B f32 (2D tensor, 128x64 box) for chunk c.
__device__ __forceinline__ void tma_chunk(uint32_t bufb, uint32_t mbar,
                                          const CUtensorMap* tmap,
                                          int c, int m0, int n0) {
    asm volatile("mbarrier.arrive.expect_tx.shared.b64 _, [%0], %1;"
                 :: "r"(mbar), "r"(65536u) : "memory");
    const char* srcA = reinterpret_cast<const char*>(g_xh)
                     + (size_t)c * 65536 + (m0 >> 7) * 32768;
    asm volatile(
        "cp.async.bulk.shared::cluster.global.mbarrier::complete_tx::bytes "
        "[%0], [%1], %2, [%3];"
        :: "r"(bufb), "l"(srcA), "r"(32768u), "r"(mbar) : "memory");
    asm volatile(
        "cp.async.bulk.tensor.2d.shared::cluster.global.tile.mbarrier::complete_tx::bytes "
        "[%0], [%1, {%2, %3}], [%4];"
        :: "r"(bufb + BSTG), "l"(tmap), "r"(c * 128), "r"(n0), "r"(mbar)
        : "memory");
}

__global__ void __launch_bounds__(256, 1) gemm_kernel(
    float* __restrict__ y, const __grid_constant__ CUtensorMap tmap) {
    extern __shared__ __align__(1024) char smem[];
    const uint32_t sb = smem_u32(smem);
    const int tid = threadIdx.x, lane = tid & 31, wid = tid >> 5;
    const int wm = wid >> 1, wn = wid & 1;          // warp grid 4(M) x 2(N)
    const int n0 = blockIdx.x * 64;
    const int m0 = blockIdx.y * 128;
    const int nb = n0 >> 6;

    if (tid < 3)
        asm volatile("mbarrier.init.shared.b64 [%0], 1;"
                     :: "r"(sb + tid * 8) : "memory");
    __syncthreads();
    if (tid == 0) {
        tma_chunk(sb + SM_BUF + 0 * BUF, sb + 0,  &tmap, 0, m0, n0);
        tma_chunk(sb + SM_BUF + 1 * BUF, sb + 8,  &tmap, 1, m0, n0);
        tma_chunk(sb + SM_BUF + 2 * BUF, sb + 16, &tmap, 2, m0, n0);
    }

    float acc[2][4][4];
    #pragma unroll
    for (int i = 0; i < 2; ++i)
        #pragma unroll
        for (int j = 0; j < 4; ++j)
            #pragma unroll
            for (int q = 0; q < 4; ++q) acc[i][j][q] = 0.f;

    const int rl = lane & 15;
    const uint32_t kh16 = (uint32_t)(lane >> 4) * 16;
    const uint32_t arow0 = (uint32_t)(wm * 32 + rl) * 128;
    const uint32_t arow1 = arow0 + 16 * 128;
    const uint32_t brow0 = (uint32_t)(wn * 32 + rl) * 128;
    const uint32_t brow1 = brow0 + 16 * 128;
    // cvt mapping: warp handles rows wid*8..wid*8+7; lane covers f32 cols
    // 4*lane..4*lane+3 -> f16 sub (lane>>4), byte (8*lane)&127
    const uint32_t cv_sub  = (uint32_t)(lane >> 4) * 8192;
    const uint32_t cv_boff = ((uint32_t)lane * 8) & 127;

    // ---- patch+cvt helpers (inline lambdas via macros of locals) ----
    #define PATCH_F32(stageoff, chunk) do {                                       \
        const int _bk = (chunk) * 64 + nb;                                       \
        const int _cnt = min(g_bcnt[_bk], 1024);                                 \
        for (int _j = tid; _j < _cnt; _j += 256) {                               \
            const unsigned _e = g_bdata[_bk * 1024 + _j];                        \
            const int _lp = _e >> 16, _col = _lp & 127, _row = _lp >> 7;         \
            *reinterpret_cast<float*>(smem + (stageoff) + _row * 512 + _col * 4) \
                = __half2float(__ushort_as_half((unsigned short)(_e & 0xFFFF))); \
        }                                                                        \
    } while (0)

    #define CVT_B(stageoff, bf16base) do {                                        \
        _Pragma("unroll")                                                        \
        for (int _it = 0; _it < 8; ++_it) {                                      \
            const int _row = wid * 8 + _it;                                      \
            float4 _v = *reinterpret_cast<const float4*>(                        \
                smem + (stageoff) + _row * 512 + lane * 16);                     \
            __half2 _h01 = __floats2half2_rn(_v.x, _v.y);                        \
            __half2 _h23 = __floats2half2_rn(_v.z, _v.w);                        \
            const uint32_t _u0 = *reinterpret_cast<uint32_t*>(&_h01);            \
            const uint32_t _u1 = *reinterpret_cast<uint32_t*>(&_h23);            \
            const uint32_t _ad = (bf16base) + cv_sub                             \
                               + SW128((uint32_t)_row * 128 + cv_boff);          \
            asm volatile("st.shared.v2.b32 [%0], {%1, %2};"                      \
                         :: "r"(_ad), "r"(_u0), "r"(_u1) : "memory");            \
        }                                                                        \
    } while (0)

    // prologue: prep chunk 0
    MBAR_WAIT(sb + 0, 0);
    PATCH_F32(SM_BUF + 0 * BUF + BSTG, 0);
    __syncthreads();
    CVT_B(SM_BUF + 0 * BUF + BSTG, sb + SM_BF16);
    __syncthreads();

    for (int c = 0; c < NC; ++c) {
        const int b = c % 3;
        const uint32_t ab = sb + SM_BUF + (uint32_t)b * BUF;
        const uint32_t bf = sb + SM_BF16 + (uint32_t)(c & 1) * 16384;

        #pragma unroll
        for (int ks = 0; ks < 8; ++ks) {
            const uint32_t sub_a = ab + (ks >> 2) * A_SUB;
            const uint32_t sub_b = bf + (ks >> 2) * 8192;
            const uint32_t kb = (uint32_t)(ks & 3) * 32 + kh16;
            uint32_t ah[2][4], bh[2][4];
            ldsm4(ah[0], sub_a + SW128(arow0 + kb));
            ldsm4(ah[1], sub_a + SW128(arow1 + kb));
            ldsm4(bh[0], sub_b + SW128(brow0 + kb));
            ldsm4(bh[1], sub_b + SW128(brow1 + kb));
            #pragma unroll
            for (int mi = 0; mi < 2; ++mi)
                #pragma unroll
                for (int nj = 0; nj < 2; ++nj) {
                    mma16816(acc[mi][nj*2+0], ah[mi], bh[nj][0], bh[nj][2]);
                    mma16816(acc[mi][nj*2+1], ah[mi], bh[nj][1], bh[nj][3]);
                }
        }

        if (c + 1 < NC) {
            const int b1 = (c + 1) % 3;
            MBAR_WAIT(sb + b1 * 8, ((c + 1) / 3) & 1);
            PATCH_F32(SM_BUF + b1 * BUF + BSTG, c + 1);
            __syncthreads();   // patch -> cvt ordering
            CVT_B(SM_BUF + b1 * BUF + BSTG, sb + SM_BF16 + ((c + 1) & 1) * 16384);
        }
        __syncthreads();       // cvt visible; buffer b fully consumed
        if (tid == 0 && c + 3 < NC)
            tma_chunk(sb + SM_BUF + b * BUF, sb + b * 8, &tmap, c + 3, m0, n0);
    }

    #pragma unroll
    for (int mi = 0; mi < 2; ++mi) {
        const int row0 = m0 + wm * 32 + mi * 16 + (lane >> 2);
        #pragma unroll
        for (int nbk = 0; nbk < 4; ++nbk) {
            const int col = n0 + wn * 32 + nbk * 8 + (lane & 3) * 2;
            *reinterpret_cast<float2*>(y + (size_t)row0 * O_DIM + col) =
                make_float2(acc[mi][nbk][0], acc[mi][nbk][1]);
            *reinterpret_cast<float2*>(y + (size_t)(row0 + 8) * O_DIM + col) =
                make_float2(acc[mi][nbk][2], acc[mi][nbk][3]);
        }
    }
    #undef PATCH_F32
    #undef CVT_B
}

// ============================================================================
extern "C" void kernel_launch(void* const* d_in, const int* in_sizes, int n_in,
                              void* d_out, int out_size) {
    const float* x    = (const float*)d_in[0];
    const float* w    = (const float*)d_in[1];
    const int*   flip = (const int*)d_in[2];   // JAX x64 disabled -> int32
    const float* vals = (const float*)d_in[3];
    float*       y    = (float*)d_out;
    const int nflip = in_sizes[2];

    stage1_kernel<<<NB_WIN + NB_CX + 1, 256>>>(
        reinterpret_cast<const float4*>(x), flip, nflip);
    scatter_kernel<<<(nflip + 2047) / 2048, 256>>>(flip, vals, nflip);

    // Build 2D tensormap for raw f32 W (no -lcuda: fetch driver entry point)
    CUtensorMap tmap;
    {
        typedef CUresult (*EncFn)(
            CUtensorMap*, CUtensorMapDataType, cuuint32_t, void*,
            const cuuint64_t*, const cuuint64_t*, const cuuint32_t*,
            const cuuint32_t*, CUtensorMapInterleave, CUtensorMapSwizzle,
            CUtensorMapL2promotion, CUtensorMapFloatOOBfill);
        void* fn = nullptr;
        cudaDriverEntryPointQueryResult qr;
        cudaGetDriverEntryPointByVersion("cuTensorMapEncodeTiled", &fn, 12000,
                                         cudaEnableDefault, &qr);
        cuuint64_t dims[2]    = {4096, 4096};
        cuuint64_t strides[1] = {16384};
        cuuint32_t box[2]     = {128, 64};
        cuuint32_t es[2]      = {1, 1};
        ((EncFn)fn)(&tmap, CU_TENSOR_MAP_DATA_TYPE_FLOAT32, 2, (void*)w,
                    dims, strides, box, es,
                    CU_TENSOR_MAP_INTERLEAVE_NONE, CU_TENSOR_MAP_SWIZZLE_NONE,
                    CU_TENSOR_MAP_L2_PROMOTION_L2_128B,
                    CU_TENSOR_MAP_FLOAT_OOB_FILL_NONE);
    }

    cudaFuncSetAttribute(gemm_kernel, cudaFuncAttributeMaxDynamicSharedMemorySize,
                         GEMM_SMEM);
    gemm_kernel<<<dim3(O_DIM / 64, B_ROWS / 128, 1), 256, GEMM_SMEM>>>(y, tmap);
}

// round 16
// speedup vs baseline: 1.6485x; 1.6485x over previous
#include <cuda_runtime.h>
#include <cuda_fp16.h>
#include <cstdint>

// ============================================================================
// y = x @ W_mod^T ; W_mod = W with values*0.1 scattered at flip_idx (last wins)
// R16: R14 GEMM (frozen) + bitmask dedup: winner election via 2MB L2-resident
// claim/dup bitmasks instead of 1M atomicMax RMWs over the 64MB aux array.
//   stage1: claim-or + dup-or | x->f16 | W->f16   (chunk-major swizzled)
//   K2: unique -> plain wh store; dup -> atomicMax(aux) (only ~60K atomics)
//   K3: dup winners -> wh store + aux zero-restore
//   masks restored via cudaMemsetAsync (capturable, allocation-free)
// ============================================================================

#define O_DIM  4096
#define I_DIM  4096
#define B_ROWS 256
#define W_ELEMS (O_DIM * I_DIM)
#define X_ELEMS (B_ROWS * I_DIM)

#define SW128(b) ((b) ^ (((b) >> 3) & 0x70))

__device__ __align__(16) __half g_xh[X_ELEMS];
__device__ __align__(16) __half g_wh[W_ELEMS];
// dup-position winner tokens; zero at module load; K3 restores zeros
__device__ int g_aux[W_ELEMS];
// claim + dup bitmasks (2MB each, L2-resident); zero at load; memset restores
__device__ unsigned g_mask1[W_ELEMS / 32];
__device__ unsigned g_mask2[W_ELEMS / 32];

// ----------------------------------------------------------------------------
// Stage 1: fused [bitmask claim/dup | x convert | W convert]
// ----------------------------------------------------------------------------
static constexpr int NB_WIN = 977;                 // ceil(1e6/1024), 4 idx/thr
static constexpr int NB_CX  = X_ELEMS / 4 / 256;   // 1024
static constexpr int NB_CW  = W_ELEMS / 4 / 256;   // 16384

__device__ __forceinline__ void claim(int pos) {
    const unsigned bit = 1u << (pos & 31);
    const unsigned old = atomicOr(&g_mask1[pos >> 5], bit);
    if (old & bit) atomicOr(&g_mask2[pos >> 5], bit);
}

__global__ void __launch_bounds__(256) stage1_kernel(
    const float4* __restrict__ x, const float4* __restrict__ w,
    const int* __restrict__ flip, int n) {
    const int bid = blockIdx.x, tid = threadIdx.x;
    if (bid < NB_WIN) {
        const int base = bid * 1024 + tid * 4;
        if (base + 3 < n) {
            const int4 f = *reinterpret_cast<const int4*>(flip + base);
            claim(f.x); claim(f.y); claim(f.z); claim(f.w);
        } else {
            for (int k = 0; k < 4; ++k)
                if (base + k < n) claim(flip[base + k]);
        }
    } else if (bid < NB_WIN + NB_CX) {
        const int i = (bid - NB_WIN) * 256 + tid;
        const int m = i >> 10, kq = (i & 1023) << 2;
        float4 v = __ldcs(x + i);
        uint2 p = make_uint2(
            (uint32_t)__half_as_ushort(__float2half_rn(v.x)) |
            ((uint32_t)__half_as_ushort(__float2half_rn(v.y)) << 16),
            (uint32_t)__half_as_ushort(__float2half_rn(v.z)) |
            ((uint32_t)__half_as_ushort(__float2half_rn(v.w)) << 16));
        const int c = kq >> 7, k0 = kq & 127, sub = k0 >> 6, kk = k0 & 63;
        char* dst = reinterpret_cast<char*>(g_xh)
                  + (size_t)c * 65536 + (m >> 7) * 32768 + sub * 16384
                  + SW128((m & 127) * 128 + kk * 2);
        __stcs(reinterpret_cast<uint2*>(dst), p);
    } else {
        const int i = (bid - NB_WIN - NB_CX) * 256 + tid;
        const int o = i >> 10, kq = (i & 1023) << 2;
        float4 v = __ldcs(w + i);
        uint2 p = make_uint2(
            (uint32_t)__half_as_ushort(__float2half_rn(v.x)) |
            ((uint32_t)__half_as_ushort(__float2half_rn(v.y)) << 16),
            (uint32_t)__half_as_ushort(__float2half_rn(v.z)) |
            ((uint32_t)__half_as_ushort(__float2half_rn(v.w)) << 16));
        const int c = kq >> 7, k0 = kq & 127, sub = k0 >> 6, kk = k0 & 63;
        char* dst = reinterpret_cast<char*>(g_wh)
                  + (size_t)c * 1048576 + (o >> 6) * 16384 + sub * 8192
                  + SW128((o & 63) * 128 + kk * 2);
        __stcs(reinterpret_cast<uint2*>(dst), p);
    }
}

// ----------------------------------------------------------------------------
// K2: unique flips -> plain wh store; dup flips -> atomicMax(aux)
// K3: dup winners -> wh store; restore aux zeros
// ----------------------------------------------------------------------------
__device__ __forceinline__ void wh_write(int pos, float v) {
    const int o = pos >> 12, k = pos & 4095;
    const int c = k >> 7, k0 = k & 127, sub = k0 >> 6, kk = k0 & 63;
    char* dst = reinterpret_cast<char*>(g_wh)
              + (size_t)c * 1048576 + (o >> 6) * 16384 + sub * 8192
              + SW128((o & 63) * 128 + kk * 2);
    *reinterpret_cast<__half*>(dst) = __float2half_rn(v);
}

__global__ void __launch_bounds__(256) scatter_a_kernel(
    const int* __restrict__ flip, const float* __restrict__ vals, int n) {
    const int base = (blockIdx.x * 256 + threadIdx.x) * 8;
    if (base + 7 < n) {
        const int4 f0 = *reinterpret_cast<const int4*>(flip + base);
        const int4 f1 = *reinterpret_cast<const int4*>(flip + base + 4);
        const float4 v0 = *reinterpret_cast<const float4*>(vals + base);
        const float4 v1 = *reinterpret_cast<const float4*>(vals + base + 4);
        const int   pos[8] = {f0.x, f0.y, f0.z, f0.w, f1.x, f1.y, f1.z, f1.w};
        const float val[8] = {v0.x, v0.y, v0.z, v0.w, v1.x, v1.y, v1.z, v1.w};
        unsigned m2[8];
        #pragma unroll
        for (int k = 0; k < 8; ++k) m2[k] = g_mask2[pos[k] >> 5];
        #pragma unroll
        for (int k = 0; k < 8; ++k) {
            if ((m2[k] >> (pos[k] & 31)) & 1u)
                atomicMax(&g_aux[pos[k]], base + k + 1);   // duplicate position
            else
                wh_write(pos[k], val[k] * 0.1f);            // unique owner
        }
    } else {
        for (int k = 0; k < 8; ++k)
            if (base + k < n) {
                const int p = flip[base + k];
                if ((g_mask2[p >> 5] >> (p & 31)) & 1u)
                    atomicMax(&g_aux[p], base + k + 1);
                else
                    wh_write(p, vals[base + k] * 0.1f);
            }
    }
}

__global__ void __launch_bounds__(256) scatter_b_kernel(
    const int* __restrict__ flip, const float* __restrict__ vals, int n) {
    const int base = (blockIdx.x * 256 + threadIdx.x) * 8;
    if (base + 7 < n) {
        const int4 f0 = *reinterpret_cast<const int4*>(flip + base);
        const int4 f1 = *reinterpret_cast<const int4*>(flip + base + 4);
        const int pos[8] = {f0.x, f0.y, f0.z, f0.w, f1.x, f1.y, f1.z, f1.w};
        #pragma unroll
        for (int k = 0; k < 8; ++k) {
            if ((g_mask2[pos[k] >> 5] >> (pos[k] & 31)) & 1u) {
                if (g_aux[pos[k]] == base + k + 1) {        // dup winner
                    wh_write(pos[k], vals[base + k] * 0.1f);
                    g_aux[pos[k]] = 0;                      // restore invariant
                }
            }
        }
    } else {
        for (int k = 0; k < 8; ++k)
            if (base + k < n) {
                const int p = flip[base + k];
                if ((g_mask2[p >> 5] >> (p & 31)) & 1u) {
                    if (g_aux[p] == base + k + 1) {
                        wh_write(p, vals[base + k] * 0.1f);
                        g_aux[p] = 0;
                    }
                }
            }
    }
}

// ============================================================================
// Stage 3: GEMM (R14-exact). CTA 128x64, K-chunk 128, 4-deep TMA pipeline,
// block barrier every 2 chunks with dual reissue.
// ============================================================================
static constexpr int A_SUB = 16384;
static constexpr int B_OFF = 32768;
static constexpr int B_SUB = 8192;
static constexpr int BUF   = 49152;
static constexpr int SM_TILES = 1024;
static constexpr int GEMM_SMEM = SM_TILES + 4 * BUF;   // 197632
static constexpr int NC    = I_DIM / 128;   // 32 chunks

__device__ __forceinline__ uint32_t smem_u32(const void* p) {
    uint32_t a;
    asm("{ .reg .u64 t; cvta.to.shared.u64 t, %1; cvt.u32.u64 %0, t; }"
        : "=r"(a) : "l"(p));
    return a;
}
__device__ __forceinline__ void ldsm4(uint32_t* r, uint32_t addr) {
    asm volatile("ldmatrix.sync.aligned.m8n8.x4.shared.b16 {%0,%1,%2,%3}, [%4];"
                 : "=r"(r[0]), "=r"(r[1]), "=r"(r[2]), "=r"(r[3]) : "r"(addr));
}
__device__ __forceinline__ void mma16816(float* c, const uint32_t* a,
                                         uint32_t b0, uint32_t b1) {
    asm volatile(
        "mma.sync.aligned.m16n8k16.row.col.f32.f16.f16.f32 "
        "{%0,%1,%2,%3}, {%4,%5,%6,%7}, {%8,%9}, {%0,%1,%2,%3};"
        : "+f"(c[0]), "+f"(c[1]), "+f"(c[2]), "+f"(c[3])
        : "r"(a[0]), "r"(a[1]), "r"(a[2]), "r"(a[3]), "r"(b0), "r"(b1));
}

#define MBAR_WAIT(mbar_addr, phase) do {                                         \
    uint32_t _mbar = (uint32_t)(mbar_addr);                                      \
    uint32_t _parity = (uint32_t)(phase);                                        \
    uint32_t _done;                                                              \
    asm volatile(                                                                \
        "{\n\t.reg .pred p;\n\t"                                                 \
        "mbarrier.try_wait.parity.acquire.cta.shared::cta.b64 p, [%1], %2;\n\t"  \
        "selp.b32 %0, 1, 0, p;\n\t}"                                             \
        : "=r"(_done) : "r"(_mbar), "r"(_parity) : "memory");                    \
    if (!_done) {                                                                \
        asm volatile(                                                            \
            "{\n\t.reg .pred P1;\n\t"                                            \
            "WL_%=:\n\t"                                                         \
            "mbarrier.try_wait.parity.acquire.cta.shared::cta.b64 P1, [%0], %1, 0x989680;\n\t" \
            "@P1 bra.uni WD_%=;\n\t"                                             \
            "bra.uni WL_%=;\n\t"                                                 \
            "WD_%=:\n\t}"                                                        \
            :: "r"(_mbar), "r"(_parity) : "memory");                             \
    }                                                                            \
} while (0)

__device__ __forceinline__ void tma_chunk(uint32_t bufb, uint32_t mbar,
                                          int c, int m0, int n0) {
    asm volatile("mbarrier.arrive.expect_tx.shared.b64 _, [%0], %1;"
                 :: "r"(mbar), "r"(49152u) : "memory");
    const char* srcA = reinterpret_cast<const char*>(g_xh)
                     + (size_t)c * 65536 + (m0 >> 7) * 32768;
    const char* srcB = reinterpret_cast<const char*>(g_wh)
                     + (size_t)c * 1048576 + (n0 >> 6) * 16384;
    asm volatile(
        "cp.async.bulk.shared::cluster.global.mbarrier::complete_tx::bytes "
        "[%0], [%1], %2, [%3];"
        :: "r"(bufb), "l"(srcA), "r"(32768u), "r"(mbar) : "memory");
    asm volatile(
        "cp.async.bulk.shared::cluster.global.mbarrier::complete_tx::bytes "
        "[%0], [%1], %2, [%3];"
        :: "r"(bufb + B_OFF), "l"(srcB), "r"(16384u), "r"(mbar) : "memory");
}

__global__ void __launch_bounds__(256, 1) gemm_kernel(float* __restrict__ y) {
    extern __shared__ __align__(1024) char smem[];
    const uint32_t sb = smem_u32(smem);
    const int tid = threadIdx.x, lane = tid & 31, wid = tid >> 5;
    const int wm = wid >> 1, wn = wid & 1;
    const int n0 = blockIdx.x * 64;
    const int m0 = blockIdx.y * 128;

    if (tid < 4)
        asm volatile("mbarrier.init.shared.b64 [%0], 1;"
                     :: "r"(sb + tid * 8) : "memory");
    __syncthreads();
    if (tid == 0) {
        tma_chunk(sb + SM_TILES + 0 * BUF, sb + 0,  0, m0, n0);
        tma_chunk(sb + SM_TILES + 1 * BUF, sb + 8,  1, m0, n0);
        tma_chunk(sb + SM_TILES + 2 * BUF, sb + 16, 2, m0, n0);
        tma_chunk(sb + SM_TILES + 3 * BUF, sb + 24, 3, m0, n0);
    }

    float acc[2][4][4];
    #pragma unroll
    for (int i = 0; i < 2; ++i)
        #pragma unroll
        for (int j = 0; j < 4; ++j)
            #pragma unroll
            for (int q = 0; q < 4; ++q) acc[i][j][q] = 0.f;

    const int rl = lane & 15;
    const uint32_t kh16 = (uint32_t)(lane >> 4) * 16;
    const uint32_t arow0 = (uint32_t)(wm * 32 + rl) * 128;
    const uint32_t arow1 = arow0 + 16 * 128;
    const uint32_t brow0 = (uint32_t)(wn * 32 + rl) * 128;
    const uint32_t brow1 = brow0 + 16 * 128;

    for (int c = 0; c < NC; ++c) {
        const int b = c & 3;
        MBAR_WAIT(sb + b * 8, (c >> 2) & 1);
        const uint32_t bb = sb + SM_TILES + b * BUF;

        #pragma unroll
        for (int ks = 0; ks < 8; ++ks) {
            const uint32_t sub_a = bb + (ks >> 2) * A_SUB;
            const uint32_t sub_b = bb + B_OFF + (ks >> 2) * B_SUB;
            const uint32_t kb = (uint32_t)(ks & 3) * 32 + kh16;
            uint32_t ah[2][4], bh[2][4];
            ldsm4(ah[0], sub_a + SW128(arow0 + kb));
            ldsm4(ah[1], sub_a + SW128(arow1 + kb));
            ldsm4(bh[0], sub_b + SW128(brow0 + kb));
            ldsm4(bh[1], sub_b + SW128(brow1 + kb));
            #pragma unroll
            for (int mi = 0; mi < 2; ++mi)
                #pragma unroll
                for (int nj = 0; nj < 2; ++nj) {
                    mma16816(acc[mi][nj*2+0], ah[mi], bh[nj][0], bh[nj][2]);
                    mma16816(acc[mi][nj*2+1], ah[mi], bh[nj][1], bh[nj][3]);
                }
        }
        if (c & 1) {
            __syncthreads();
            if (tid == 0) {
                if (c + 3 < NC)
                    tma_chunk(sb + SM_TILES + ((c + 3) & 3) * BUF,
                              sb + ((c + 3) & 3) * 8, c + 3, m0, n0);
                if (c + 4 < NC)
                    tma_chunk(sb + SM_TILES + ((c + 4) & 3) * BUF,
                              sb + ((c + 4) & 3) * 8, c + 4, m0, n0);
            }
        }
    }

    #pragma unroll
    for (int mi = 0; mi < 2; ++mi) {
        const int row0 = m0 + wm * 32 + mi * 16 + (lane >> 2);
        #pragma unroll
        for (int nb = 0; nb < 4; ++nb) {
            const int col = n0 + wn * 32 + nb * 8 + (lane & 3) * 2;
            *reinterpret_cast<float2*>(y + (size_t)row0 * O_DIM + col) =
                make_float2(acc[mi][nb][0], acc[mi][nb][1]);
            *reinterpret_cast<float2*>(y + (size_t)(row0 + 8) * O_DIM + col) =
                make_float2(acc[mi][nb][2], acc[mi][nb][3]);
        }
    }
}

// ============================================================================
extern "C" void kernel_launch(void* const* d_in, const int* in_sizes, int n_in,
                              void* d_out, int out_size) {
    const float* x    = (const float*)d_in[0];
    const float* w    = (const float*)d_in[1];
    const int*   flip = (const int*)d_in[2];   // JAX x64 disabled -> int32
    const float* vals = (const float*)d_in[3];
    float*       y    = (float*)d_out;
    const int nflip = in_sizes[2];
    const int nb8 = (nflip + 2047) / 2048;

    stage1_kernel<<<NB_WIN + NB_CX + NB_CW, 256>>>(
        reinterpret_cast<const float4*>(x), reinterpret_cast<const float4*>(w),
        flip, nflip);
    scatter_a_kernel<<<nb8, 256>>>(flip, vals, nflip);
    scatter_b_kernel<<<nb8, 256>>>(flip, vals, nflip);

    cudaFuncSetAttribute(gemm_kernel, cudaFuncAttributeMaxDynamicSharedMemorySize,
                         GEMM_SMEM);
    gemm_kernel<<<dim3(O_DIM / 64, B_ROWS / 128, 1), 256, GEMM_SMEM>>>(y);

    // restore bitmask zero-invariant (graph-capturable, allocation-free)
    void* m1 = nullptr; void* m2 = nullptr;
    cudaGetSymbolAddress(&m1, g_mask1);
    cudaGetSymbolAddress(&m2, g_mask2);
    cudaMemsetAsync(m1, 0, sizeof(unsigned) * (W_ELEMS / 32));
    cudaMemsetAsync(m2, 0, sizeof(unsigned) * (W_ELEMS / 32));
}